// round 11
// baseline (speedup 1.0000x reference)
#include <cuda_runtime.h>
#include <cuda_bf16.h>
#include <cstdint>

// Problem shapes (fixed by setup_inputs)
#define B_      4
#define L_      8192
#define BLOCK_  128
#define NB_     (L_ / BLOCK_)          // 64
#define V_      32000
#define D_      1024
#define NT_     (L_ + NB_)             // 8256 new_tokens per batch row

// Output layout (flattened tuple, row-major, float32):
//   [0,        B*NT)                new_tokens      (33024)
//   [OFF_CE,   OFF_CE + B*NB*D)     cat_emb         (262144)
//   [OFF_H,    OFF_H  + B*NB*V)     hist            (8192000)
#define OFF_CE  (B_ * NT_)                         // 33024
#define OFF_H   (OFF_CE + B_ * NB_ * D_)           // 295168

#define QUARTERS 4
#define QF32     (V_ / QUARTERS)                   // 8000 bins per quarter
#define QF4      (QF32 / 4)                        // 2000 float4 per quarter
#define NWORDS   (QF32 / 32)                       // 250 bitmap words
#define GRID_    (B_ * NB_ * QUARTERS)             // 1024 CTAs, one wave

// Fused kernel with BITMAP histogram: prologue touches ~1.3 KB of SMEM
// instead of 64 KB, so the coalesced STG.128 drain starts almost
// immediately and dominates the kernel (pure store stream).
// CTA (bj, q):
//   1. zero 250-word bitmap (+ overflow counter)
//   2. atomicOr presence bits for the block's tokens in this quarter;
//      duplicates go to an exact overflow list (capacity 128 = worst case)
//   3. expand bits -> float4 in registers, stream to global (STG.128)
//   4. (q==0) cat_emb row copy + new_tokens
__global__ __launch_bounds__(256)
void chunk_agg_bitmap(const int* __restrict__ tokens,
                      const float* __restrict__ catW,
                      float* __restrict__ out)
{
    __shared__ uint32_t bm[NWORDS];      // 1000 B
    __shared__ int      ov_tok[BLOCK_];  // overflow rel-bins (worst case 127)
    __shared__ int      ov_cnt;

    const int bid = blockIdx.x;
    const int q   = bid & (QUARTERS - 1);
    const int bj  = bid >> 2;            // 0..255
    const int b   = bj >> 6;
    const int j   = bj & 63;
    const int tid = threadIdx.x;

    // ---- 1) zero bitmap + overflow counter
    if (tid < NWORDS) bm[tid] = 0u;
    if (tid == 255)   ov_cnt = 0;

    const int* __restrict__ blk = tokens + b * L_ + j * BLOCK_;

    // ---- 4) side outputs (q==0 CTA only; small, overlapped)
    if (q == 0) {
        const int t0 = blk[0];
        const float4* __restrict__ src =
            reinterpret_cast<const float4*>(catW + (size_t)t0 * D_);
        float4* __restrict__ dst =
            reinterpret_cast<float4*>(out + OFF_CE + bj * D_);
        dst[tid] = src[tid];             // 1024 f32 = 256 float4

        if (tid < BLOCK_)
            out[b * NT_ + NB_ + j * BLOCK_ + tid] = (float)blk[tid];
        if (tid == 0)
            out[b * NT_ + j] = (float)t0;
    }

    __syncthreads();

    // ---- 2) set presence bits; exact duplicate handling via overflow list
    if (tid < BLOCK_) {
        const int tok = blk[tid];
        const int lo  = q * QF32;
        if (tok >= lo && tok < lo + QF32) {
            const int rel = tok - lo;
            const uint32_t mask = 1u << (rel & 31);
            const uint32_t old  = atomicOr(&bm[rel >> 5], mask);
            if (old & mask) {                       // duplicate token value
                const int k = atomicAdd(&ov_cnt, 1);
                ov_tok[k] = rel;
            }
        }
    }

    __syncthreads();

    // ---- 3) pure store stream: expand bitmap -> float4, coalesced STG.128
    float* __restrict__ histq =
        out + OFF_H + (size_t)bj * V_ + q * QF32;
    float4* __restrict__ h4 = reinterpret_cast<float4*>(histq);
    const int novf = ov_cnt;

    if (novf == 0) {
        // common path: zero arithmetic beyond the bit expansion
        #pragma unroll 8
        for (int i = tid; i < QF4; i += 256) {
            const uint32_t bits = (bm[i >> 3] >> ((i & 7) << 2)) & 0xFu;
            float4 v;
            v.x = (bits & 1u) ? 1.0f : 0.0f;
            v.y = (bits & 2u) ? 1.0f : 0.0f;
            v.z = (bits & 4u) ? 1.0f : 0.0f;
            v.w = (bits & 8u) ? 1.0f : 0.0f;
            h4[i] = v;
        }
    } else {
        #pragma unroll 4
        for (int i = tid; i < QF4; i += 256) {
            const uint32_t bits = (bm[i >> 3] >> ((i & 7) << 2)) & 0xFu;
            float4 v;
            v.x = (bits & 1u) ? 1.0f : 0.0f;
            v.y = (bits & 2u) ? 1.0f : 0.0f;
            v.z = (bits & 4u) ? 1.0f : 0.0f;
            v.w = (bits & 8u) ? 1.0f : 0.0f;
            for (int e = 0; e < novf; ++e) {
                const int rel = ov_tok[e];
                if ((rel >> 2) == i) {
                    switch (rel & 3) {
                        case 0: v.x += 1.0f; break;
                        case 1: v.y += 1.0f; break;
                        case 2: v.z += 1.0f; break;
                        default: v.w += 1.0f; break;
                    }
                }
            }
            h4[i] = v;
        }
    }
}

extern "C" void kernel_launch(void* const* d_in, const int* in_sizes, int n_in,
                              void* d_out, int out_size)
{
    const int*   tokens = (const int*)  d_in[0];   // [4, 8192] int32
    const float* catW   = (const float*)d_in[1];   // [32000, 1024] f32
    // d_in[2] (num_embed_W) is a dead lookup in the reference — unused.
    float* out = (float*)d_out;

    chunk_agg_bitmap<<<GRID_, 256>>>(tokens, catW, out);
}